// round 9
// baseline (speedup 1.0000x reference)
#include <cuda_runtime.h>
#include <cstdint>
#include <cstddef>

#define NN 100000
#define NE 1600000
#define SCAN_B ((NN + 255) / 256)   // 391

typedef unsigned long long ull;

// ---------------- scratch (device globals) ----------------
static __device__ float  g_y[(size_t)NN * 384];     // t buffers [N, K*in] / decoder hidden
static __device__ float  g_h1[(size_t)NN * 128];    // h1
static __device__ float  g_h2[(size_t)NN * 64];     // h2; later z
static __device__ float4 g_ecsr[NE];                // CSR-ordered {c0,c1,c2, src-as-bits}
static __device__ int    g_off[NN + 1];
static __device__ int    g_cur[NN];
static __device__ int    g_deg[NN];
static __device__ float  g_dinv[NN];
static __device__ float  g_w3T[192 * 128];          // [k*64+i][mu 0..63 | logvar 64..127]
static __device__ int    g_bsum[512];
static __device__ int    g_boff[512];
static __device__ int    g_is64;

// ---------------- fused prep ----------------
__global__ void k_prep(const int* __restrict__ ei32, const float* __restrict__ mw,
                       const float* __restrict__ lw) {
    int idx = blockIdx.x * 256 + threadIdx.x;
    if (blockIdx.x == 0) {
        int nz = (ei32[2 * threadIdx.x + 1] != 0) ? 1 : 0;
        int any = __syncthreads_or(nz);
        if (threadIdx.x == 0) g_is64 = any ? 0 : 1;
    }
    if (idx < 3 * 64 * 64) {
        int o = idx & 63;
        int r = idx >> 6;
        g_w3T[r * 128 + o]      = mw[idx];
        g_w3T[r * 128 + 64 + o] = lw[idx];
    }
    if (idx < NN) g_deg[idx] = 0;
}

__device__ __forceinline__ int load_idx(const void* eiv, size_t pos) {
    if (g_is64) return (int)((const long long*)eiv)[pos];
    return ((const int*)eiv)[pos];
}

__global__ void k_deg(const void* __restrict__ eiv) {
    int e = blockIdx.x * blockDim.x + threadIdx.x;
    if (e >= NE) return;
    int d = load_idx(eiv, (size_t)NE + e);
    d = min(max(d, 0), NN - 1);
    atomicAdd(&g_deg[d], 1);
}

// ---------------- two-level scan ----------------
__global__ void k_scan1() {
    __shared__ int ws[8];
    int i = blockIdx.x * 256 + threadIdx.x;
    int lane = threadIdx.x & 31, wid = threadIdx.x >> 5;
    int v = (i < NN) ? g_deg[i] : 0;
    int s = v;
#pragma unroll
    for (int o = 1; o < 32; o <<= 1) {
        int t = __shfl_up_sync(0xFFFFFFFFu, s, o);
        if (lane >= o) s += t;
    }
    if (lane == 31) ws[wid] = s;
    __syncthreads();
    if (threadIdx.x == 0) {
        int tot = 0;
#pragma unroll
        for (int w = 0; w < 8; w++) tot += ws[w];
        g_bsum[blockIdx.x] = tot;
    }
}

__global__ void k_scan2() {
    __shared__ int ws[16];
    int tid = threadIdx.x, lane = tid & 31, wid = tid >> 5;
    int v = (tid < SCAN_B) ? g_bsum[tid] : 0;
    int s = v;
#pragma unroll
    for (int o = 1; o < 32; o <<= 1) {
        int t = __shfl_up_sync(0xFFFFFFFFu, s, o);
        if (lane >= o) s += t;
    }
    if (lane == 31) ws[wid] = s;
    __syncthreads();
    if (wid == 0 && lane < 16) {
        int a = ws[lane];
        int si = a;
#pragma unroll
        for (int o = 1; o < 16; o <<= 1) {
            int t = __shfl_up_sync(0xFFFFu, si, o);
            if (lane >= o) si += t;
        }
        ws[lane] = si - a;
    }
    __syncthreads();
    int incl = ws[wid] + s;
    if (tid < SCAN_B) g_boff[tid] = incl - v;
    if (tid == SCAN_B - 1) g_off[NN] = incl;
}

__global__ void k_scan3() {
    __shared__ int ws[8];
    int i = blockIdx.x * 256 + threadIdx.x;
    int lane = threadIdx.x & 31, wid = threadIdx.x >> 5;
    int v = (i < NN) ? g_deg[i] : 0;
    int s = v;
#pragma unroll
    for (int o = 1; o < 32; o <<= 1) {
        int t = __shfl_up_sync(0xFFFFFFFFu, s, o);
        if (lane >= o) s += t;
    }
    if (lane == 31) ws[wid] = s;
    __syncthreads();
    if (wid == 0 && lane < 8) {
        int a = ws[lane];
        int si = a;
#pragma unroll
        for (int o = 1; o < 8; o <<= 1) {
            int t = __shfl_up_sync(0xFFu, si, o);
            if (lane >= o) si += t;
        }
        ws[lane] = si - a;
    }
    __syncthreads();
    if (i < NN) {
        int excl = g_boff[blockIdx.x] + ws[wid] + s - v;
        g_off[i] = excl;
        g_cur[i] = excl;
        g_dinv[i] = 1.0f / fmaxf((float)v, 1.0f);
    }
}

__global__ void k_place(const void* __restrict__ eiv, const float* __restrict__ pseudo) {
    int e = blockIdx.x * blockDim.x + threadIdx.x;
    if (e >= NE) return;
    int s = load_idx(eiv, e);
    int d = load_idx(eiv, (size_t)NE + e);
    s = min(max(s, 0), NN - 1);
    d = min(max(d, 0), NN - 1);
    float p  = pseudo[e];
    float v  = p * 3.0f;
    float fl = floorf(v);
    float f  = v - fl;
    int bot  = ((int)fl) % 3;
    float b0 = 0.5f * f * f - f + 0.5f;
    float b1 = -f * f + f + 0.5f;
    float b2 = 0.5f * f * f;
    float c0, c1, c2;
    if (bot == 0)      { c0 = b0; c1 = b1; c2 = b2; }
    else if (bot == 1) { c0 = b2; c1 = b0; c2 = b1; }
    else               { c0 = b1; c1 = b2; c2 = b0; }
    int pos = atomicAdd(&g_cur[d], 1);
    g_ecsr[pos] = make_float4(c0, c1, c2, __int_as_float(s));
}

// ---------------- CSR in-domain aggregation, unroll x4 ----------------
#define AGG_FMA(a0, a1, a2, m, v)                                            \
    a0.x += m.x * v.x; a0.y += m.x * v.y; a0.z += m.x * v.z; a0.w += m.x * v.w; \
    a1.x += m.y * v.x; a1.y += m.y * v.y; a1.z += m.y * v.z; a1.w += m.y * v.w; \
    a2.x += m.z * v.x; a2.y += m.z * v.y; a2.z += m.z * v.z; a2.w += m.z * v.w;

__global__ void k_agg64(const float* __restrict__ h, float* __restrict__ t) {
    int lane = threadIdx.x & 15;
    int dst  = (blockIdx.x * blockDim.x + threadIdx.x) >> 4;
    if (dst >= NN) return;
    int p = g_off[dst], end = g_off[dst + 1];
    float4 a0 = make_float4(0.f, 0.f, 0.f, 0.f), a1 = a0, a2 = a0;
    for (; p + 3 < end; p += 4) {
        float4 m0 = g_ecsr[p], m1 = g_ecsr[p + 1], m2 = g_ecsr[p + 2], m3 = g_ecsr[p + 3];
        float4 v0 = *reinterpret_cast<const float4*>(h + ((size_t)__float_as_int(m0.w)) * 64 + lane * 4);
        float4 v1 = *reinterpret_cast<const float4*>(h + ((size_t)__float_as_int(m1.w)) * 64 + lane * 4);
        float4 v2 = *reinterpret_cast<const float4*>(h + ((size_t)__float_as_int(m2.w)) * 64 + lane * 4);
        float4 v3 = *reinterpret_cast<const float4*>(h + ((size_t)__float_as_int(m3.w)) * 64 + lane * 4);
        AGG_FMA(a0, a1, a2, m0, v0)
        AGG_FMA(a0, a1, a2, m1, v1)
        AGG_FMA(a0, a1, a2, m2, v2)
        AGG_FMA(a0, a1, a2, m3, v3)
    }
    for (; p < end; p++) {
        float4 m = g_ecsr[p];
        float4 v = *reinterpret_cast<const float4*>(h + ((size_t)__float_as_int(m.w)) * 64 + lane * 4);
        AGG_FMA(a0, a1, a2, m, v)
    }
    float4* tr = reinterpret_cast<float4*>(t + (size_t)dst * 192);
    tr[lane] = a0; tr[16 + lane] = a1; tr[32 + lane] = a2;
}

__global__ void k_agg128(const float* __restrict__ h, float* __restrict__ t) {
    int lane = threadIdx.x & 31;
    int dst  = (blockIdx.x * blockDim.x + threadIdx.x) >> 5;
    if (dst >= NN) return;
    int p = g_off[dst], end = g_off[dst + 1];
    float4 a0 = make_float4(0.f, 0.f, 0.f, 0.f), a1 = a0, a2 = a0;
    for (; p + 3 < end; p += 4) {
        float4 m0 = g_ecsr[p], m1 = g_ecsr[p + 1], m2 = g_ecsr[p + 2], m3 = g_ecsr[p + 3];
        float4 v0 = *reinterpret_cast<const float4*>(h + ((size_t)__float_as_int(m0.w)) * 128 + lane * 4);
        float4 v1 = *reinterpret_cast<const float4*>(h + ((size_t)__float_as_int(m1.w)) * 128 + lane * 4);
        float4 v2 = *reinterpret_cast<const float4*>(h + ((size_t)__float_as_int(m2.w)) * 128 + lane * 4);
        float4 v3 = *reinterpret_cast<const float4*>(h + ((size_t)__float_as_int(m3.w)) * 128 + lane * 4);
        AGG_FMA(a0, a1, a2, m0, v0)
        AGG_FMA(a0, a1, a2, m1, v1)
        AGG_FMA(a0, a1, a2, m2, v2)
        AGG_FMA(a0, a1, a2, m3, v3)
    }
    for (; p < end; p++) {
        float4 m = g_ecsr[p];
        float4 v = *reinterpret_cast<const float4*>(h + ((size_t)__float_as_int(m.w)) * 128 + lane * 4);
        AGG_FMA(a0, a1, a2, m, v)
    }
    float4* tr = reinterpret_cast<float4*>(t + (size_t)dst * 384);
    tr[lane] = a0; tr[32 + lane] = a1; tr[64 + lane] = a2;
}

// ---------------- TF32 tensor-core GEMM with hi/lo error compensation ----------------
// C[M,TN] = A[M,K] @ B[K,TN]. TM=128, TK=32, 256 thr = 8 warps x 16 rows.
// Each element split x = hi + lo (tf32 each); D = Ah*Bh + Al*Bh + Ah*Bl (fp32 accum).
// epi: 0 none, 1 bias+relu, 2 bias, 3 row-scale dinv, 4 fused mu/logvar/z (TN=128)
__device__ __forceinline__ uint32_t f2tf(float x) {
    uint32_t r;
    asm("cvt.rna.tf32.f32 %0, %1;" : "=r"(r) : "f"(x));
    return r;
}

#define MMA_TF32(d, a, b)                                                     \
    asm volatile("mma.sync.aligned.m16n8k8.row.col.f32.tf32.tf32.f32 "        \
                 "{%0,%1,%2,%3}, {%4,%5,%6,%7}, {%8,%9}, {%0,%1,%2,%3};"      \
                 : "+f"(d[0]), "+f"(d[1]), "+f"(d[2]), "+f"(d[3])             \
                 : "r"(a[0]), "r"(a[1]), "r"(a[2]), "r"(a[3]),                \
                   "r"(b[0]), "r"(b[1]))

template <int TN>
__global__ __launch_bounds__(256, 2) void k_gemm3(
    const float* __restrict__ A, const float* __restrict__ B,
    const float* __restrict__ bias, float* __restrict__ C, int M, int K, int epi,
    const float* __restrict__ eps, float* __restrict__ outmlv, float* __restrict__ zout) {
    constexpr int NT  = TN / 8;                 // n-tiles per warp
    constexpr int ASZ = 8 * 4 * 32 * 4;         // 4096 floats per (hi|lo)
    constexpr int BSZ = 4 * NT * 32 * 2;        // per (hi|lo)
    extern __shared__ float smem[];
    float* AFh = smem;
    float* AFl = AFh + ASZ;
    float* BFh = AFl + ASZ;
    float* BFl = BFh + BSZ;

    int tid  = threadIdx.x;
    int w    = tid >> 5;
    int lane = tid & 31;
    int gid  = lane >> 2;
    int cq   = lane & 3;
    int m0   = blockIdx.x * 128;

    float acc[NT][4];
#pragma unroll
    for (int nt = 0; nt < NT; nt++)
#pragma unroll
        for (int r = 0; r < 4; r++) acc[nt][r] = 0.0f;

    for (int kc = 0; kc < K; kc += 32) {
        __syncthreads();   // previous chunk's frags fully consumed
        // ---- stage A (128x32), pre-fragmented m16n8k8 layout, hi/lo split ----
#pragma unroll
        for (int i = 0; i < 4; i++) {
            int s  = tid + i * 256;          // float4 slot 0..1023
            int m  = s >> 3;                 // row 0..127
            int kq = s & 7;                  // float4 within row
            float4 v = make_float4(0.f, 0.f, 0.f, 0.f);
            if (m0 + m < M) v = *reinterpret_cast<const float4*>(&A[(size_t)(m0 + m) * K + kc + kq * 4]);
            int wm = m >> 4, r16 = m & 15, g = r16 & 7, h8 = r16 >> 3;
            int ks = kq >> 1, kb = (kq & 1) * 2;
            float e[4] = {v.x, v.y, v.z, v.w};
#pragma unroll
            for (int j = 0; j < 4; j++) {
                uint32_t hi = f2tf(e[j]);
                uint32_t lo = f2tf(e[j] - __uint_as_float(hi));
                int idx = ((wm * 4 + ks) * 32 + g * 4 + j) * 4 + h8 + kb;
                AFh[idx] = __uint_as_float(hi);
                AFl[idx] = __uint_as_float(lo);
            }
        }
        // ---- stage B (32xTN) ----
#pragma unroll
        for (int i = 0; i < TN / 32; i++) {
            int s  = tid + i * 256;          // float4 slot, total 8*TN
            int kr = s / (TN / 4);
            int nq = s % (TN / 4);
            float4 v = *reinterpret_cast<const float4*>(&B[(size_t)(kc + kr) * TN + nq * 4]);
            int ks = kr >> 3, kk = kr & 7;
            int lk = kk & 3, rg = kk >> 2;
            int nb = (nq & 1) * 4, nt = nq >> 1;
            float e[4] = {v.x, v.y, v.z, v.w};
#pragma unroll
            for (int j = 0; j < 4; j++) {
                uint32_t hi = f2tf(e[j]);
                uint32_t lo = f2tf(e[j] - __uint_as_float(hi));
                int idx = ((ks * NT + nt) * 32 + (nb + j) * 4 + lk) * 2 + rg;
                BFh[idx] = __uint_as_float(hi);
                BFl[idx] = __uint_as_float(lo);
            }
        }
        __syncthreads();
        // ---- compute: 4 k-steps of m16n8k8 ----
#pragma unroll
        for (int ks = 0; ks < 4; ks++) {
            float4 ahv = *reinterpret_cast<const float4*>(&AFh[((w * 4 + ks) * 32 + lane) * 4]);
            float4 alv = *reinterpret_cast<const float4*>(&AFl[((w * 4 + ks) * 32 + lane) * 4]);
            uint32_t ah[4] = {__float_as_uint(ahv.x), __float_as_uint(ahv.y),
                              __float_as_uint(ahv.z), __float_as_uint(ahv.w)};
            uint32_t al[4] = {__float_as_uint(alv.x), __float_as_uint(alv.y),
                              __float_as_uint(alv.z), __float_as_uint(alv.w)};
#pragma unroll
            for (int nt = 0; nt < NT; nt++) {
                float2 bhv = *reinterpret_cast<const float2*>(&BFh[((ks * NT + nt) * 32 + lane) * 2]);
                float2 blv = *reinterpret_cast<const float2*>(&BFl[((ks * NT + nt) * 32 + lane) * 2]);
                uint32_t bh[2] = {__float_as_uint(bhv.x), __float_as_uint(bhv.y)};
                uint32_t bl[2] = {__float_as_uint(blv.x), __float_as_uint(blv.y)};
                MMA_TF32(acc[nt], ah, bh);
                MMA_TF32(acc[nt], al, bh);
                MMA_TF32(acc[nt], ah, bl);
            }
        }
    }

    // ---------------- epilogue ----------------
    if (epi == 4) {   // TN==128: mu cols 0..63, logvar cols 64..127
        const size_t n64 = (size_t)NN * 64;
#pragma unroll
        for (int r2 = 0; r2 < 2; r2++) {
            int m = m0 + w * 16 + gid + r2 * 8;
            if (m >= M) continue;
            float rs = g_dinv[m];
#pragma unroll
            for (int nt = 0; nt < NT / 2; nt++) {
                int col = nt * 8 + cq * 2;
                float mu0 = acc[nt][r2 * 2 + 0] * rs;
                float mu1 = acc[nt][r2 * 2 + 1] * rs;
                float lv0 = acc[nt + NT / 2][r2 * 2 + 0] * rs;
                float lv1 = acc[nt + NT / 2][r2 * 2 + 1] * rs;
                float2 ev = *reinterpret_cast<const float2*>(&eps[(size_t)m * 64 + col]);
                float z0 = mu0 + ev.x * expf(0.5f * lv0);
                float z1 = mu1 + ev.y * expf(0.5f * lv1);
                *reinterpret_cast<float2*>(&outmlv[n64 + (size_t)m * 64 + col])     = make_float2(mu0, mu1);
                *reinterpret_cast<float2*>(&outmlv[2 * n64 + (size_t)m * 64 + col]) = make_float2(lv0, lv1);
                *reinterpret_cast<float2*>(&zout[(size_t)m * 64 + col])             = make_float2(z0, z1);
            }
        }
        return;
    }
#pragma unroll
    for (int r2 = 0; r2 < 2; r2++) {
        int m = m0 + w * 16 + gid + r2 * 8;
        if (m >= M) continue;
        float rs = (epi == 3) ? g_dinv[m] : 1.0f;
#pragma unroll
        for (int nt = 0; nt < NT; nt++) {
            int col = nt * 8 + cq * 2;
            float v0 = acc[nt][r2 * 2 + 0];
            float v1 = acc[nt][r2 * 2 + 1];
            if (epi == 1 || epi == 2) { v0 += bias[col]; v1 += bias[col + 1]; }
            v0 *= rs; v1 *= rs;
            if (epi == 1) { v0 = fmaxf(v0, 0.f); v1 = fmaxf(v1, 0.f); }
            *reinterpret_cast<float2*>(&C[(size_t)m * TN + col]) = make_float2(v0, v1);
        }
    }
}

// ---------------- launch ----------------
extern "C" void kernel_launch(void* const* d_in, const int* in_sizes, int n_in,
                              void* d_out, int out_size) {
    const float* x      = (const float*)d_in[0];
    const float* pseudo = (const float*)d_in[1];
    const float* w1     = (const float*)d_in[2];   // [3][64][128] == W1cat [192][128]
    const float* w2     = (const float*)d_in[3];   // [3][128][64] == W2cat [384][64]
    const float* mu_w   = (const float*)d_in[4];
    const float* lv_w   = (const float*)d_in[5];
    const float* d1_w   = (const float*)d_in[6];   // [64][128]
    const float* d1_b   = (const float*)d_in[7];
    const float* d2_w   = (const float*)d_in[8];   // [128][64]
    const float* d2_b   = (const float*)d_in[9];
    const float* eps    = (const float*)d_in[10];
    const void*  ei     = d_in[11];
    float*       out    = (float*)d_out;

    float *py, *ph1, *ph2, *pw3T;
    cudaGetSymbolAddress((void**)&py,   g_y);
    cudaGetSymbolAddress((void**)&ph1,  g_h1);
    cudaGetSymbolAddress((void**)&ph2,  g_h2);
    cudaGetSymbolAddress((void**)&pw3T, g_w3T);

    const int GB = (NN + 127) / 128;
    const int SM128 = (8 * 4 * 32 * 4 * 2 + 4 * 16 * 32 * 2 * 2) * 4;  // 65536
    const int SM64  = (8 * 4 * 32 * 4 * 2 + 4 * 8  * 32 * 2 * 2) * 4;  // 49152
    cudaFuncSetAttribute(k_gemm3<128>, cudaFuncAttributeMaxDynamicSharedMemorySize, SM128);
    cudaFuncSetAttribute(k_gemm3<64>,  cudaFuncAttributeMaxDynamicSharedMemorySize, SM64);

    // --- edge preprocessing: degrees -> CSR offsets -> placement ---
    k_prep<<<SCAN_B, 256>>>((const int*)ei, mu_w, lv_w);
    k_deg<<<(NE + 255) / 256, 256>>>(ei);
    k_scan1<<<SCAN_B, 256>>>();
    k_scan2<<<1, 512>>>();
    k_scan3<<<SCAN_B, 256>>>();
    k_place<<<(NE + 255) / 256, 256>>>(ei, pseudo);

    // --- layer 1: t1 = agg(x); h1 = (t1 @ w1) * dinv ---
    k_agg64<<<(NN * 16 + 255) / 256, 256>>>(x, py);
    k_gemm3<128><<<GB, 256, SM128>>>(py, w1, nullptr, ph1, NN, 192, 3, nullptr, nullptr, nullptr);

    // --- layer 2: t2 = agg(h1); h2 = (t2 @ w2) * dinv ---
    k_agg128<<<(NN * 32 + 255) / 256, 256>>>(ph1, py);
    k_gemm3<64><<<GB, 256, SM64>>>(py, w2, nullptr, ph2, NN, 384, 3, nullptr, nullptr, nullptr);

    // --- layer 3+4: t3 = agg(h2); fused epilogue: mu/logvar -> out, z -> g_h2 ---
    k_agg64<<<(NN * 16 + 255) / 256, 256>>>(ph2, py);
    k_gemm3<128><<<GB, 256, SM128>>>(py, pw3T, nullptr, nullptr, NN, 192, 4, eps, out, ph2);

    // --- decoder: rec = relu(z @ d1_w + d1_b) @ d2_w + d2_b ---
    k_gemm3<128><<<GB, 256, SM128>>>(ph2, d1_w, d1_b, py, NN, 64, 1, nullptr, nullptr, nullptr);
    k_gemm3<64><<<GB, 256, SM64>>>(py, d2_w, d2_b, out, NN, 128, 2, nullptr, nullptr, nullptr);
}

// round 10
// speedup vs baseline: 1.1669x; 1.1669x over previous
#include <cuda_runtime.h>
#include <cstdint>
#include <cstddef>

#define NN 100000
#define NE 1600000
#define SCAN_B ((NN + 255) / 256)   // 391
#define CHUNK 25600                 // 200 GEMM blocks per chunk; t chunk stays L2-resident

typedef unsigned long long ull;

// ---------------- scratch (device globals) ----------------
static __device__ float  g_y[(size_t)CHUNK * 384];  // per-chunk t buffer / decoder hidden (L2-hot)
static __device__ float  g_h1[(size_t)NN * 128];    // h1; later z [N,64]
static __device__ float  g_h2[(size_t)NN * 64];     // h2
static __device__ float4 g_ecsr[NE];                // CSR-ordered {c0,c1,c2, src-as-bits}
static __device__ int    g_off[NN + 1];
static __device__ int    g_cur[NN];
static __device__ int    g_deg[NN];
static __device__ float  g_dinv[NN];
static __device__ float  g_w3T[192 * 128];          // [k*64+i][mu 0..63 | logvar 64..127]
static __device__ int    g_bsum[512];
static __device__ int    g_boff[512];
static __device__ int    g_is64;

// ---------------- fused prep: dtype detect + w3 interleave + zero degrees ----------------
__global__ void k_prep(const int* __restrict__ ei32, const float* __restrict__ mw,
                       const float* __restrict__ lw) {
    int idx = blockIdx.x * 256 + threadIdx.x;
    if (blockIdx.x == 0) {
        int nz = (ei32[2 * threadIdx.x + 1] != 0) ? 1 : 0;
        int any = __syncthreads_or(nz);
        if (threadIdx.x == 0) g_is64 = any ? 0 : 1;
    }
    if (idx < 3 * 64 * 64) {
        int o = idx & 63;
        int r = idx >> 6;
        g_w3T[r * 128 + o]      = mw[idx];
        g_w3T[r * 128 + 64 + o] = lw[idx];
    }
    if (idx < NN) g_deg[idx] = 0;
}

__device__ __forceinline__ int load_idx(const void* eiv, size_t pos) {
    if (g_is64) return (int)((const long long*)eiv)[pos];
    return ((const int*)eiv)[pos];
}

__global__ void k_deg(const void* __restrict__ eiv) {
    int e = blockIdx.x * blockDim.x + threadIdx.x;
    if (e >= NE) return;
    int d = load_idx(eiv, (size_t)NE + e);
    d = min(max(d, 0), NN - 1);
    atomicAdd(&g_deg[d], 1);
}

// ---------------- two-level scan ----------------
__global__ void k_scan1() {
    __shared__ int ws[8];
    int i = blockIdx.x * 256 + threadIdx.x;
    int lane = threadIdx.x & 31, wid = threadIdx.x >> 5;
    int v = (i < NN) ? g_deg[i] : 0;
    int s = v;
#pragma unroll
    for (int o = 1; o < 32; o <<= 1) {
        int t = __shfl_up_sync(0xFFFFFFFFu, s, o);
        if (lane >= o) s += t;
    }
    if (lane == 31) ws[wid] = s;
    __syncthreads();
    if (threadIdx.x == 0) {
        int tot = 0;
#pragma unroll
        for (int w = 0; w < 8; w++) tot += ws[w];
        g_bsum[blockIdx.x] = tot;
    }
}

__global__ void k_scan2() {
    __shared__ int ws[16];
    int tid = threadIdx.x, lane = tid & 31, wid = tid >> 5;
    int v = (tid < SCAN_B) ? g_bsum[tid] : 0;
    int s = v;
#pragma unroll
    for (int o = 1; o < 32; o <<= 1) {
        int t = __shfl_up_sync(0xFFFFFFFFu, s, o);
        if (lane >= o) s += t;
    }
    if (lane == 31) ws[wid] = s;
    __syncthreads();
    if (wid == 0 && lane < 16) {
        int a = ws[lane];
        int si = a;
#pragma unroll
        for (int o = 1; o < 16; o <<= 1) {
            int t = __shfl_up_sync(0xFFFFu, si, o);
            if (lane >= o) si += t;
        }
        ws[lane] = si - a;
    }
    __syncthreads();
    int incl = ws[wid] + s;
    if (tid < SCAN_B) g_boff[tid] = incl - v;
    if (tid == SCAN_B - 1) g_off[NN] = incl;
}

__global__ void k_scan3() {
    __shared__ int ws[8];
    int i = blockIdx.x * 256 + threadIdx.x;
    int lane = threadIdx.x & 31, wid = threadIdx.x >> 5;
    int v = (i < NN) ? g_deg[i] : 0;
    int s = v;
#pragma unroll
    for (int o = 1; o < 32; o <<= 1) {
        int t = __shfl_up_sync(0xFFFFFFFFu, s, o);
        if (lane >= o) s += t;
    }
    if (lane == 31) ws[wid] = s;
    __syncthreads();
    if (wid == 0 && lane < 8) {
        int a = ws[lane];
        int si = a;
#pragma unroll
        for (int o = 1; o < 8; o <<= 1) {
            int t = __shfl_up_sync(0xFFu, si, o);
            if (lane >= o) si += t;
        }
        ws[lane] = si - a;
    }
    __syncthreads();
    if (i < NN) {
        int excl = g_boff[blockIdx.x] + ws[wid] + s - v;
        g_off[i] = excl;
        g_cur[i] = excl;
        g_dinv[i] = 1.0f / fmaxf((float)v, 1.0f);
    }
}

__global__ void k_place(const void* __restrict__ eiv, const float* __restrict__ pseudo) {
    int e = blockIdx.x * blockDim.x + threadIdx.x;
    if (e >= NE) return;
    int s = load_idx(eiv, e);
    int d = load_idx(eiv, (size_t)NE + e);
    s = min(max(s, 0), NN - 1);
    d = min(max(d, 0), NN - 1);
    float p  = pseudo[e];
    float v  = p * 3.0f;
    float fl = floorf(v);
    float f  = v - fl;
    int bot  = ((int)fl) % 3;
    float b0 = 0.5f * f * f - f + 0.5f;
    float b1 = -f * f + f + 0.5f;
    float b2 = 0.5f * f * f;
    float c0, c1, c2;
    if (bot == 0)      { c0 = b0; c1 = b1; c2 = b2; }
    else if (bot == 1) { c0 = b2; c1 = b0; c2 = b1; }
    else               { c0 = b1; c1 = b2; c2 = b0; }
    int pos = atomicAdd(&g_cur[d], 1);
    g_ecsr[pos] = make_float4(c0, c1, c2, __int_as_float(s));
}

// ---------------- CSR in-domain aggregation (chunked dst range), unroll x4 ----------------
#define AGG_FMA(a0, a1, a2, m, v)                                            \
    a0.x += m.x * v.x; a0.y += m.x * v.y; a0.z += m.x * v.z; a0.w += m.x * v.w; \
    a1.x += m.y * v.x; a1.y += m.y * v.y; a1.z += m.y * v.z; a1.w += m.y * v.w; \
    a2.x += m.z * v.x; a2.y += m.z * v.y; a2.z += m.z * v.z; a2.w += m.z * v.w;

__global__ void k_agg64(const float* __restrict__ h, float* __restrict__ t,
                        int dst0, int ndst) {
    int lane = threadIdx.x & 15;
    int li   = (blockIdx.x * blockDim.x + threadIdx.x) >> 4;
    if (li >= ndst) return;
    int dst = dst0 + li;
    int p = g_off[dst], end = g_off[dst + 1];
    float4 a0 = make_float4(0.f, 0.f, 0.f, 0.f), a1 = a0, a2 = a0;
    for (; p + 3 < end; p += 4) {
        float4 m0 = g_ecsr[p], m1 = g_ecsr[p + 1], m2 = g_ecsr[p + 2], m3 = g_ecsr[p + 3];
        float4 v0 = *reinterpret_cast<const float4*>(h + ((size_t)__float_as_int(m0.w)) * 64 + lane * 4);
        float4 v1 = *reinterpret_cast<const float4*>(h + ((size_t)__float_as_int(m1.w)) * 64 + lane * 4);
        float4 v2 = *reinterpret_cast<const float4*>(h + ((size_t)__float_as_int(m2.w)) * 64 + lane * 4);
        float4 v3 = *reinterpret_cast<const float4*>(h + ((size_t)__float_as_int(m3.w)) * 64 + lane * 4);
        AGG_FMA(a0, a1, a2, m0, v0)
        AGG_FMA(a0, a1, a2, m1, v1)
        AGG_FMA(a0, a1, a2, m2, v2)
        AGG_FMA(a0, a1, a2, m3, v3)
    }
    for (; p < end; p++) {
        float4 m = g_ecsr[p];
        float4 v = *reinterpret_cast<const float4*>(h + ((size_t)__float_as_int(m.w)) * 64 + lane * 4);
        AGG_FMA(a0, a1, a2, m, v)
    }
    float4* tr = reinterpret_cast<float4*>(t + (size_t)li * 192);
    tr[lane] = a0; tr[16 + lane] = a1; tr[32 + lane] = a2;
}

__global__ void k_agg128(const float* __restrict__ h, float* __restrict__ t,
                         int dst0, int ndst) {
    int lane = threadIdx.x & 31;
    int li   = (blockIdx.x * blockDim.x + threadIdx.x) >> 5;
    if (li >= ndst) return;
    int dst = dst0 + li;
    int p = g_off[dst], end = g_off[dst + 1];
    float4 a0 = make_float4(0.f, 0.f, 0.f, 0.f), a1 = a0, a2 = a0;
    for (; p + 3 < end; p += 4) {
        float4 m0 = g_ecsr[p], m1 = g_ecsr[p + 1], m2 = g_ecsr[p + 2], m3 = g_ecsr[p + 3];
        float4 v0 = *reinterpret_cast<const float4*>(h + ((size_t)__float_as_int(m0.w)) * 128 + lane * 4);
        float4 v1 = *reinterpret_cast<const float4*>(h + ((size_t)__float_as_int(m1.w)) * 128 + lane * 4);
        float4 v2 = *reinterpret_cast<const float4*>(h + ((size_t)__float_as_int(m2.w)) * 128 + lane * 4);
        float4 v3 = *reinterpret_cast<const float4*>(h + ((size_t)__float_as_int(m3.w)) * 128 + lane * 4);
        AGG_FMA(a0, a1, a2, m0, v0)
        AGG_FMA(a0, a1, a2, m1, v1)
        AGG_FMA(a0, a1, a2, m2, v2)
        AGG_FMA(a0, a1, a2, m3, v3)
    }
    for (; p < end; p++) {
        float4 m = g_ecsr[p];
        float4 v = *reinterpret_cast<const float4*>(h + ((size_t)__float_as_int(m.w)) * 128 + lane * 4);
        AGG_FMA(a0, a1, a2, m, v)
    }
    float4* tr = reinterpret_cast<float4*>(t + (size_t)li * 384);
    tr[lane] = a0; tr[32 + lane] = a1; tr[64 + lane] = a2;
}

// ---------------- GEMM: packed f32x2 math + register double-buffering (R7-proven) ----------------
// C[M,TN] = A[M,K] @ B[K,TN], TM=128, TK=32, 256 threads, 8 rows x TN/16 cols/thread.
// All pointers pre-offset per chunk. dinv indexed by local row.
// epi: 0 none, 1 bias+relu, 2 bias, 3 row-scale dinv, 4 fused mu/logvar/z (TN=128 only)
template <int TN>
__global__ __launch_bounds__(256, 2) void k_gemm2(
    const float* __restrict__ A, const float* __restrict__ B,
    const float* __restrict__ bias, float* __restrict__ C, int M, int K, int epi,
    const float* __restrict__ dinv, const float* __restrict__ eps,
    float* __restrict__ outmlv, float* __restrict__ zout) {
    constexpr int TK = 32;
    constexpr int NPAIR = TN / 32;
    constexpr int NB = TN / 32;
    __shared__ float As[TK * 132];
    __shared__ float Bs[TK * TN];

    int tid = threadIdx.x;
    int tx  = tid & 15;
    int ty  = tid >> 4;
    int m0  = blockIdx.x * 128;

    float  ar[16];
    float4 br[NB];

    {
#pragma unroll
        for (int i = 0; i < 16; i++) {
            int idx = tid + i * 256;
            int gm = m0 + (idx >> 5);
            ar[i] = (gm < M) ? A[(size_t)gm * K + (idx & 31)] : 0.0f;
        }
#pragma unroll
        for (int i = 0; i < NB; i++) {
            int idx = tid + i * 256;
            br[i] = *reinterpret_cast<const float4*>(&B[(size_t)(idx / (TN / 4)) * TN + (idx % (TN / 4)) * 4]);
        }
    }

    ull acc[8][NPAIR];
#pragma unroll
    for (int r = 0; r < 8; r++)
#pragma unroll
        for (int c = 0; c < NPAIR; c++) acc[r][c] = 0ull;

    for (int kc = 0; kc < K; kc += TK) {
#pragma unroll
        for (int i = 0; i < 16; i++) {
            int idx = tid + i * 256;
            As[(idx & 31) * 132 + (idx >> 5)] = ar[i];
        }
#pragma unroll
        for (int i = 0; i < NB; i++) {
            int idx = tid + i * 256;
            *reinterpret_cast<float4*>(&Bs[(idx / (TN / 4)) * TN + (idx % (TN / 4)) * 4]) = br[i];
        }
        __syncthreads();
        if (kc + TK < K) {
            int kn = kc + TK;
#pragma unroll
            for (int i = 0; i < 16; i++) {
                int idx = tid + i * 256;
                int gm = m0 + (idx >> 5);
                ar[i] = (gm < M) ? A[(size_t)gm * K + kn + (idx & 31)] : 0.0f;
            }
#pragma unroll
            for (int i = 0; i < NB; i++) {
                int idx = tid + i * 256;
                br[i] = *reinterpret_cast<const float4*>(&B[(size_t)(kn + idx / (TN / 4)) * TN + (idx % (TN / 4)) * 4]);
            }
        }
#pragma unroll 8
        for (int k = 0; k < TK; k++) {
            float4 a0 = *reinterpret_cast<const float4*>(&As[k * 132 + ty * 8]);
            float4 a1 = *reinterpret_cast<const float4*>(&As[k * 132 + ty * 8 + 4]);
            float am[8] = {a0.x, a0.y, a0.z, a0.w, a1.x, a1.y, a1.z, a1.w};
            ull ap[8];
#pragma unroll
            for (int r = 0; r < 8; r++)
                asm("mov.b64 %0, {%1, %1};" : "=l"(ap[r]) : "f"(am[r]));
            ulonglong2 b0 = *reinterpret_cast<const ulonglong2*>(&Bs[k * TN + tx * 4]);
#pragma unroll
            for (int r = 0; r < 8; r++) {
                asm("fma.rn.f32x2 %0, %1, %2, %0;" : "+l"(acc[r][0]) : "l"(ap[r]), "l"(b0.x));
                asm("fma.rn.f32x2 %0, %1, %2, %0;" : "+l"(acc[r][1]) : "l"(ap[r]), "l"(b0.y));
            }
            if (TN == 128) {
                ulonglong2 b1 = *reinterpret_cast<const ulonglong2*>(&Bs[k * TN + 64 + tx * 4]);
#pragma unroll
                for (int r = 0; r < 8; r++) {
                    asm("fma.rn.f32x2 %0, %1, %2, %0;" : "+l"(acc[r][NPAIR - 2]) : "l"(ap[r]), "l"(b1.x));
                    asm("fma.rn.f32x2 %0, %1, %2, %0;" : "+l"(acc[r][NPAIR - 1]) : "l"(ap[r]), "l"(b1.y));
                }
            }
        }
        __syncthreads();
    }

    // ---------------- epilogue ----------------
    if (epi == 4) {  // fused: mu | logvar -> outmlv(+n64/+2*n64), z -> zout  (TN==128)
        const size_t n64 = (size_t)NN * 64;
#pragma unroll
        for (int r = 0; r < 8; r++) {
            int m = m0 + ty * 8 + r;
            if (m >= M) continue;
            float rs = dinv[m];
            float mu0, mu1, mu2, mu3, lv0, lv1, lv2, lv3;
            asm("mov.b64 {%0, %1}, %2;" : "=f"(mu0), "=f"(mu1) : "l"(acc[r][0]));
            asm("mov.b64 {%0, %1}, %2;" : "=f"(mu2), "=f"(mu3) : "l"(acc[r][1]));
            asm("mov.b64 {%0, %1}, %2;" : "=f"(lv0), "=f"(lv1) : "l"(acc[r][NPAIR - 2]));
            asm("mov.b64 {%0, %1}, %2;" : "=f"(lv2), "=f"(lv3) : "l"(acc[r][NPAIR - 1]));
            mu0 *= rs; mu1 *= rs; mu2 *= rs; mu3 *= rs;
            lv0 *= rs; lv1 *= rs; lv2 *= rs; lv3 *= rs;
            size_t base = (size_t)m * 64 + tx * 4;
            float4 ev = *reinterpret_cast<const float4*>(&eps[base]);
            float4 zv;
            zv.x = mu0 + ev.x * expf(0.5f * lv0);
            zv.y = mu1 + ev.y * expf(0.5f * lv1);
            zv.z = mu2 + ev.z * expf(0.5f * lv2);
            zv.w = mu3 + ev.w * expf(0.5f * lv3);
            *reinterpret_cast<float4*>(&outmlv[n64 + base])     = make_float4(mu0, mu1, mu2, mu3);
            *reinterpret_cast<float4*>(&outmlv[2 * n64 + base]) = make_float4(lv0, lv1, lv2, lv3);
            *reinterpret_cast<float4*>(&zout[base]) = zv;
        }
        return;
    }

    float4 bv0 = make_float4(0.f, 0.f, 0.f, 0.f), bv1 = bv0;
    if (epi == 1 || epi == 2) {
        bv0 = *reinterpret_cast<const float4*>(&bias[tx * 4]);
        if (TN == 128) bv1 = *reinterpret_cast<const float4*>(&bias[64 + tx * 4]);
    }
#pragma unroll
    for (int r = 0; r < 8; r++) {
        int m = m0 + ty * 8 + r;
        if (m >= M) continue;
        float rs = (epi == 3) ? dinv[m] : 1.0f;
        float f0, f1, f2, f3;
        asm("mov.b64 {%0, %1}, %2;" : "=f"(f0), "=f"(f1) : "l"(acc[r][0]));
        asm("mov.b64 {%0, %1}, %2;" : "=f"(f2), "=f"(f3) : "l"(acc[r][1]));
        float4 o;
        o.x = (f0 + bv0.x) * rs;
        o.y = (f1 + bv0.y) * rs;
        o.z = (f2 + bv0.z) * rs;
        o.w = (f3 + bv0.w) * rs;
        if (epi == 1) {
            o.x = fmaxf(o.x, 0.f); o.y = fmaxf(o.y, 0.f);
            o.z = fmaxf(o.z, 0.f); o.w = fmaxf(o.w, 0.f);
        }
        *reinterpret_cast<float4*>(&C[(size_t)m * TN + tx * 4]) = o;
        if (TN == 128) {
            asm("mov.b64 {%0, %1}, %2;" : "=f"(f0), "=f"(f1) : "l"(acc[r][NPAIR - 2]));
            asm("mov.b64 {%0, %1}, %2;" : "=f"(f2), "=f"(f3) : "l"(acc[r][NPAIR - 1]));
            float4 p;
            p.x = (f0 + bv1.x) * rs;
            p.y = (f1 + bv1.y) * rs;
            p.z = (f2 + bv1.z) * rs;
            p.w = (f3 + bv1.w) * rs;
            if (epi == 1) {
                p.x = fmaxf(p.x, 0.f); p.y = fmaxf(p.y, 0.f);
                p.z = fmaxf(p.z, 0.f); p.w = fmaxf(p.w, 0.f);
            }
            *reinterpret_cast<float4*>(&C[(size_t)m * TN + 64 + tx * 4]) = p;
        }
    }
}

// ---------------- launch ----------------
extern "C" void kernel_launch(void* const* d_in, const int* in_sizes, int n_in,
                              void* d_out, int out_size) {
    const float* x      = (const float*)d_in[0];
    const float* pseudo = (const float*)d_in[1];
    const float* w1     = (const float*)d_in[2];   // [3][64][128] == W1cat [192][128]
    const float* w2     = (const float*)d_in[3];   // [3][128][64] == W2cat [384][64]
    const float* mu_w   = (const float*)d_in[4];
    const float* lv_w   = (const float*)d_in[5];
    const float* d1_w   = (const float*)d_in[6];   // [64][128]
    const float* d1_b   = (const float*)d_in[7];
    const float* d2_w   = (const float*)d_in[8];   // [128][64]
    const float* d2_b   = (const float*)d_in[9];
    const float* eps    = (const float*)d_in[10];
    const void*  ei     = d_in[11];
    float*       out    = (float*)d_out;

    float *py, *ph1, *ph2, *pw3T, *pdinv;
    cudaGetSymbolAddress((void**)&py,    g_y);
    cudaGetSymbolAddress((void**)&ph1,   g_h1);
    cudaGetSymbolAddress((void**)&ph2,   g_h2);
    cudaGetSymbolAddress((void**)&pw3T,  g_w3T);
    cudaGetSymbolAddress((void**)&pdinv, g_dinv);

    // --- edge preprocessing: degrees -> CSR offsets -> placement ---
    k_prep<<<SCAN_B, 256>>>((const int*)ei, mu_w, lv_w);
    k_deg<<<(NE + 255) / 256, 256>>>(ei);
    k_scan1<<<SCAN_B, 256>>>();
    k_scan2<<<1, 512>>>();
    k_scan3<<<SCAN_B, 256>>>();
    k_place<<<(NE + 255) / 256, 256>>>(ei, pseudo);

    // --- layer 1: per chunk: t = agg(x); h1 = (t @ w1) * dinv ---
    for (int c0 = 0; c0 < NN; c0 += CHUNK) {
        int nm = (NN - c0 < CHUNK) ? (NN - c0) : CHUNK;
        int gb = (nm + 127) / 128;
        k_agg64<<<(nm * 16 + 255) / 256, 256>>>(x, py, c0, nm);
        k_gemm2<128><<<gb, 256>>>(py, w1, nullptr, ph1 + (size_t)c0 * 128, nm, 192, 3,
                                  pdinv + c0, nullptr, nullptr, nullptr);
    }

    // --- layer 2: per chunk: t = agg(h1); h2 = (t @ w2) * dinv ---
    for (int c0 = 0; c0 < NN; c0 += CHUNK) {
        int nm = (NN - c0 < CHUNK) ? (NN - c0) : CHUNK;
        int gb = (nm + 127) / 128;
        k_agg128<<<(nm * 32 + 255) / 256, 256>>>(ph1, py, c0, nm);
        k_gemm2<64><<<gb, 256>>>(py, w2, nullptr, ph2 + (size_t)c0 * 64, nm, 384, 3,
                                 pdinv + c0, nullptr, nullptr, nullptr);
    }

    // --- layer 3+4: per chunk: t = agg(h2); mu/logvar -> out, z -> g_h1 (h2 stays intact!) ---
    for (int c0 = 0; c0 < NN; c0 += CHUNK) {
        int nm = (NN - c0 < CHUNK) ? (NN - c0) : CHUNK;
        int gb = (nm + 127) / 128;
        k_agg64<<<(nm * 16 + 255) / 256, 256>>>(ph2, py, c0, nm);
        k_gemm2<128><<<gb, 256>>>(py, pw3T, nullptr, nullptr, nm, 192, 4,
                                  pdinv + c0, eps + (size_t)c0 * 64,
                                  out + (size_t)c0 * 64, ph1 + (size_t)c0 * 64);
    }

    // --- decoder: per chunk: hid = relu(z @ d1_w + b1); rec = hid @ d2_w + b2 ---
    for (int c0 = 0; c0 < NN; c0 += CHUNK) {
        int nm = (NN - c0 < CHUNK) ? (NN - c0) : CHUNK;
        int gb = (nm + 127) / 128;
        k_gemm2<128><<<gb, 256>>>(ph1 + (size_t)c0 * 64, d1_w, d1_b, py, nm, 64, 1,
                                  nullptr, nullptr, nullptr, nullptr);
        k_gemm2<64><<<gb, 256>>>(py, d2_w, d2_b, out + (size_t)c0 * 64, nm, 128, 2,
                                 nullptr, nullptr, nullptr, nullptr);
    }
}

// round 11
// speedup vs baseline: 1.5675x; 1.3434x over previous
#include <cuda_runtime.h>
#include <cuda_fp16.h>
#include <cstdint>
#include <cstddef>

#define NN 100000
#define NE 1600000
#define SCAN_B ((NN + 255) / 256)   // 391

typedef unsigned long long ull;

// ---------------- scratch (device globals) ----------------
static __device__ float  g_y[(size_t)NN * 384];     // t buffers (t1/t3 fp32, t2 as half) / decoder hidden
static __device__ float  g_h1[(size_t)NN * 128];    // h1 (as half); later z (fp32 [N,64])
static __device__ float  g_h2[(size_t)NN * 64];     // h2 (as half)
static __device__ __half g_x16[(size_t)NN * 64];    // fp16 copy of x
static __device__ float4 g_ecsr[NE];                // CSR-ordered {c0,c1,c2, src-as-bits}
static __device__ int    g_off[NN + 1];
static __device__ int    g_cur[NN];
static __device__ int    g_deg[NN];
static __device__ float  g_dinv[NN];
static __device__ float  g_w3T[192 * 128];          // [k*64+i][mu 0..63 | logvar 64..127]
static __device__ int    g_bsum[512];
static __device__ int    g_boff[512];
static __device__ int    g_is64;

// ---------------- fused prep: dtype detect + w3 interleave + zero degrees ----------------
__global__ void k_prep(const int* __restrict__ ei32, const float* __restrict__ mw,
                       const float* __restrict__ lw) {
    int idx = blockIdx.x * 256 + threadIdx.x;
    if (blockIdx.x == 0) {
        int nz = (ei32[2 * threadIdx.x + 1] != 0) ? 1 : 0;
        int any = __syncthreads_or(nz);
        if (threadIdx.x == 0) g_is64 = any ? 0 : 1;
    }
    if (idx < 3 * 64 * 64) {
        int o = idx & 63;
        int r = idx >> 6;
        g_w3T[r * 128 + o]      = mw[idx];
        g_w3T[r * 128 + 64 + o] = lw[idx];
    }
    if (idx < NN) g_deg[idx] = 0;
}

// fp16 copy of x
__global__ void k_x16(const float* __restrict__ x) {
    int i = blockIdx.x * blockDim.x + threadIdx.x;
    if (i < NN * 32) {
        float2 v = reinterpret_cast<const float2*>(x)[i];
        reinterpret_cast<__half2*>(g_x16)[i] = __float22half2_rn(v);
    }
}

__device__ __forceinline__ int load_idx(const void* eiv, size_t pos) {
    if (g_is64) return (int)((const long long*)eiv)[pos];
    return ((const int*)eiv)[pos];
}

__global__ void k_deg(const void* __restrict__ eiv) {
    int e = blockIdx.x * blockDim.x + threadIdx.x;
    if (e >= NE) return;
    int d = load_idx(eiv, (size_t)NE + e);
    d = min(max(d, 0), NN - 1);
    atomicAdd(&g_deg[d], 1);
}

// ---------------- two-level scan ----------------
__global__ void k_scan1() {
    __shared__ int ws[8];
    int i = blockIdx.x * 256 + threadIdx.x;
    int lane = threadIdx.x & 31, wid = threadIdx.x >> 5;
    int v = (i < NN) ? g_deg[i] : 0;
    int s = v;
#pragma unroll
    for (int o = 1; o < 32; o <<= 1) {
        int t = __shfl_up_sync(0xFFFFFFFFu, s, o);
        if (lane >= o) s += t;
    }
    if (lane == 31) ws[wid] = s;
    __syncthreads();
    if (threadIdx.x == 0) {
        int tot = 0;
#pragma unroll
        for (int w = 0; w < 8; w++) tot += ws[w];
        g_bsum[blockIdx.x] = tot;
    }
}

__global__ void k_scan2() {
    __shared__ int ws[16];
    int tid = threadIdx.x, lane = tid & 31, wid = tid >> 5;
    int v = (tid < SCAN_B) ? g_bsum[tid] : 0;
    int s = v;
#pragma unroll
    for (int o = 1; o < 32; o <<= 1) {
        int t = __shfl_up_sync(0xFFFFFFFFu, s, o);
        if (lane >= o) s += t;
    }
    if (lane == 31) ws[wid] = s;
    __syncthreads();
    if (wid == 0 && lane < 16) {
        int a = ws[lane];
        int si = a;
#pragma unroll
        for (int o = 1; o < 16; o <<= 1) {
            int t = __shfl_up_sync(0xFFFFu, si, o);
            if (lane >= o) si += t;
        }
        ws[lane] = si - a;
    }
    __syncthreads();
    int incl = ws[wid] + s;
    if (tid < SCAN_B) g_boff[tid] = incl - v;
    if (tid == SCAN_B - 1) g_off[NN] = incl;
}

__global__ void k_scan3() {
    __shared__ int ws[8];
    int i = blockIdx.x * 256 + threadIdx.x;
    int lane = threadIdx.x & 31, wid = threadIdx.x >> 5;
    int v = (i < NN) ? g_deg[i] : 0;
    int s = v;
#pragma unroll
    for (int o = 1; o < 32; o <<= 1) {
        int t = __shfl_up_sync(0xFFFFFFFFu, s, o);
        if (lane >= o) s += t;
    }
    if (lane == 31) ws[wid] = s;
    __syncthreads();
    if (wid == 0 && lane < 8) {
        int a = ws[lane];
        int si = a;
#pragma unroll
        for (int o = 1; o < 8; o <<= 1) {
            int t = __shfl_up_sync(0xFFu, si, o);
            if (lane >= o) si += t;
        }
        ws[lane] = si - a;
    }
    __syncthreads();
    if (i < NN) {
        int excl = g_boff[blockIdx.x] + ws[wid] + s - v;
        g_off[i] = excl;
        g_cur[i] = excl;
        g_dinv[i] = 1.0f / fmaxf((float)v, 1.0f);
    }
}

__global__ void k_place(const void* __restrict__ eiv, const float* __restrict__ pseudo) {
    int e = blockIdx.x * blockDim.x + threadIdx.x;
    if (e >= NE) return;
    int s = load_idx(eiv, e);
    int d = load_idx(eiv, (size_t)NE + e);
    s = min(max(s, 0), NN - 1);
    d = min(max(d, 0), NN - 1);
    float p  = pseudo[e];
    float v  = p * 3.0f;
    float fl = floorf(v);
    float f  = v - fl;
    int bot  = ((int)fl) % 3;
    float b0 = 0.5f * f * f - f + 0.5f;
    float b1 = -f * f + f + 0.5f;
    float b2 = 0.5f * f * f;
    float c0, c1, c2;
    if (bot == 0)      { c0 = b0; c1 = b1; c2 = b2; }
    else if (bot == 1) { c0 = b2; c1 = b0; c2 = b1; }
    else               { c0 = b1; c1 = b2; c2 = b0; }
    int pos = atomicAdd(&g_cur[d], 1);
    g_ecsr[pos] = make_float4(c0, c1, c2, __int_as_float(s));
}

// ---------------- CSR aggregation from fp16 sources, unroll x4 ----------------
__device__ __forceinline__ float4 h4_to_f4(uint2 r) {
    float2 lo = __half22float2(*reinterpret_cast<__half2*>(&r.x));
    float2 hi = __half22float2(*reinterpret_cast<__half2*>(&r.y));
    return make_float4(lo.x, lo.y, hi.x, hi.y);
}
__device__ __forceinline__ uint2 f4_to_h4(float4 v) {
    uint2 r;
    __half2 p0 = __float22half2_rn(make_float2(v.x, v.y));
    __half2 p1 = __float22half2_rn(make_float2(v.z, v.w));
    r.x = *reinterpret_cast<uint32_t*>(&p0);
    r.y = *reinterpret_cast<uint32_t*>(&p1);
    return r;
}

#define AGG_FMA(a0, a1, a2, m, v)                                            \
    a0.x += m.x * v.x; a0.y += m.x * v.y; a0.z += m.x * v.z; a0.w += m.x * v.w; \
    a1.x += m.y * v.x; a1.y += m.y * v.y; a1.z += m.y * v.z; a1.w += m.y * v.w; \
    a2.x += m.z * v.x; a2.y += m.z * v.y; a2.z += m.z * v.z; a2.w += m.z * v.w;

// in=64 (fp16 rows, 128B), t out fp32 [dst,192]
__global__ void k_agg64h(const __half* __restrict__ h, float* __restrict__ t) {
    int lane = threadIdx.x & 15;
    int dst  = (blockIdx.x * blockDim.x + threadIdx.x) >> 4;
    if (dst >= NN) return;
    int p = g_off[dst], end = g_off[dst + 1];
    float4 a0 = make_float4(0.f, 0.f, 0.f, 0.f), a1 = a0, a2 = a0;
    const uint2* hb = reinterpret_cast<const uint2*>(h);
    for (; p + 3 < end; p += 4) {
        float4 m0 = g_ecsr[p], m1 = g_ecsr[p + 1], m2 = g_ecsr[p + 2], m3 = g_ecsr[p + 3];
        uint2 r0 = hb[((size_t)__float_as_int(m0.w)) * 16 + lane];
        uint2 r1 = hb[((size_t)__float_as_int(m1.w)) * 16 + lane];
        uint2 r2 = hb[((size_t)__float_as_int(m2.w)) * 16 + lane];
        uint2 r3 = hb[((size_t)__float_as_int(m3.w)) * 16 + lane];
        float4 v0 = h4_to_f4(r0), v1 = h4_to_f4(r1), v2 = h4_to_f4(r2), v3 = h4_to_f4(r3);
        AGG_FMA(a0, a1, a2, m0, v0)
        AGG_FMA(a0, a1, a2, m1, v1)
        AGG_FMA(a0, a1, a2, m2, v2)
        AGG_FMA(a0, a1, a2, m3, v3)
    }
    for (; p < end; p++) {
        float4 m = g_ecsr[p];
        float4 v = h4_to_f4(hb[((size_t)__float_as_int(m.w)) * 16 + lane]);
        AGG_FMA(a0, a1, a2, m, v)
    }
    float4* tr = reinterpret_cast<float4*>(t + (size_t)dst * 192);
    tr[lane] = a0; tr[16 + lane] = a1; tr[32 + lane] = a2;
}

// in=128 (fp16 rows, 256B), t out fp16 [dst,384]
__global__ void k_agg128h(const __half* __restrict__ h, __half* __restrict__ t) {
    int lane = threadIdx.x & 31;
    int dst  = (blockIdx.x * blockDim.x + threadIdx.x) >> 5;
    if (dst >= NN) return;
    int p = g_off[dst], end = g_off[dst + 1];
    float4 a0 = make_float4(0.f, 0.f, 0.f, 0.f), a1 = a0, a2 = a0;
    const uint2* hb = reinterpret_cast<const uint2*>(h);
    for (; p + 3 < end; p += 4) {
        float4 m0 = g_ecsr[p], m1 = g_ecsr[p + 1], m2 = g_ecsr[p + 2], m3 = g_ecsr[p + 3];
        uint2 r0 = hb[((size_t)__float_as_int(m0.w)) * 32 + lane];
        uint2 r1 = hb[((size_t)__float_as_int(m1.w)) * 32 + lane];
        uint2 r2 = hb[((size_t)__float_as_int(m2.w)) * 32 + lane];
        uint2 r3 = hb[((size_t)__float_as_int(m3.w)) * 32 + lane];
        float4 v0 = h4_to_f4(r0), v1 = h4_to_f4(r1), v2 = h4_to_f4(r2), v3 = h4_to_f4(r3);
        AGG_FMA(a0, a1, a2, m0, v0)
        AGG_FMA(a0, a1, a2, m1, v1)
        AGG_FMA(a0, a1, a2, m2, v2)
        AGG_FMA(a0, a1, a2, m3, v3)
    }
    for (; p < end; p++) {
        float4 m = g_ecsr[p];
        float4 v = h4_to_f4(hb[((size_t)__float_as_int(m.w)) * 32 + lane]);
        AGG_FMA(a0, a1, a2, m, v)
    }
    uint2* tr = reinterpret_cast<uint2*>(t + (size_t)dst * 384);
    tr[lane] = f4_to_h4(a0); tr[32 + lane] = f4_to_h4(a1); tr[64 + lane] = f4_to_h4(a2);
}

// ---------------- GEMM: packed f32x2 math + register double-buffering ----------------
// C[M,TN] = A[M,K] @ B[K,TN], TM=128, TK=32, 256 threads, 8 rows x TN/16 cols/thread.
// AH: A is fp16. CH: C written fp16. epi: 0 none, 1 bias+relu, 2 bias, 3 dinv-scale,
// 4 fused mu/logvar/z (TN=128, fp32 outs).
template <int TN, bool AH, bool CH>
__global__ __launch_bounds__(256, 2) void k_gemm2(
    const void* __restrict__ Ap, const float* __restrict__ B,
    const float* __restrict__ bias, void* __restrict__ Cp, int M, int K, int epi,
    const float* __restrict__ eps, float* __restrict__ outmlv, float* __restrict__ zout) {
    constexpr int TK = 32;
    constexpr int NPAIR = TN / 32;
    constexpr int NB = TN / 32;
    __shared__ float As[TK * 132];
    __shared__ float Bs[TK * TN];

    int tid = threadIdx.x;
    int tx  = tid & 15;
    int ty  = tid >> 4;
    int m0  = blockIdx.x * 128;

    float  ar[16];
    float4 br[NB];

#pragma unroll
    for (int i = 0; i < 16; i++) {
        int idx = tid + i * 256;
        int gm = m0 + (idx >> 5);
        float v = 0.0f;
        if (gm < M) {
            if (AH) v = __half2float(((const __half*)Ap)[(size_t)gm * K + (idx & 31)]);
            else    v = ((const float*)Ap)[(size_t)gm * K + (idx & 31)];
        }
        ar[i] = v;
    }
#pragma unroll
    for (int i = 0; i < NB; i++) {
        int idx = tid + i * 256;
        br[i] = *reinterpret_cast<const float4*>(&B[(size_t)(idx / (TN / 4)) * TN + (idx % (TN / 4)) * 4]);
    }

    ull acc[8][NPAIR];
#pragma unroll
    for (int r = 0; r < 8; r++)
#pragma unroll
        for (int c = 0; c < NPAIR; c++) acc[r][c] = 0ull;

    for (int kc = 0; kc < K; kc += TK) {
#pragma unroll
        for (int i = 0; i < 16; i++) {
            int idx = tid + i * 256;
            As[(idx & 31) * 132 + (idx >> 5)] = ar[i];
        }
#pragma unroll
        for (int i = 0; i < NB; i++) {
            int idx = tid + i * 256;
            *reinterpret_cast<float4*>(&Bs[(idx / (TN / 4)) * TN + (idx % (TN / 4)) * 4]) = br[i];
        }
        __syncthreads();
        if (kc + TK < K) {
            int kn = kc + TK;
#pragma unroll
            for (int i = 0; i < 16; i++) {
                int idx = tid + i * 256;
                int gm = m0 + (idx >> 5);
                float v = 0.0f;
                if (gm < M) {
                    if (AH) v = __half2float(((const __half*)Ap)[(size_t)gm * K + kn + (idx & 31)]);
                    else    v = ((const float*)Ap)[(size_t)gm * K + kn + (idx & 31)];
                }
                ar[i] = v;
            }
#pragma unroll
            for (int i = 0; i < NB; i++) {
                int idx = tid + i * 256;
                br[i] = *reinterpret_cast<const float4*>(&B[(size_t)(kn + idx / (TN / 4)) * TN + (idx % (TN / 4)) * 4]);
            }
        }
#pragma unroll 8
        for (int k = 0; k < TK; k++) {
            float4 a0 = *reinterpret_cast<const float4*>(&As[k * 132 + ty * 8]);
            float4 a1 = *reinterpret_cast<const float4*>(&As[k * 132 + ty * 8 + 4]);
            float am[8] = {a0.x, a0.y, a0.z, a0.w, a1.x, a1.y, a1.z, a1.w};
            ull ap[8];
#pragma unroll
            for (int r = 0; r < 8; r++)
                asm("mov.b64 %0, {%1, %1};" : "=l"(ap[r]) : "f"(am[r]));
            ulonglong2 b0 = *reinterpret_cast<const ulonglong2*>(&Bs[k * TN + tx * 4]);
#pragma unroll
            for (int r = 0; r < 8; r++) {
                asm("fma.rn.f32x2 %0, %1, %2, %0;" : "+l"(acc[r][0]) : "l"(ap[r]), "l"(b0.x));
                asm("fma.rn.f32x2 %0, %1, %2, %0;" : "+l"(acc[r][1]) : "l"(ap[r]), "l"(b0.y));
            }
            if (TN == 128) {
                ulonglong2 b1 = *reinterpret_cast<const ulonglong2*>(&Bs[k * TN + 64 + tx * 4]);
#pragma unroll
                for (int r = 0; r < 8; r++) {
                    asm("fma.rn.f32x2 %0, %1, %2, %0;" : "+l"(acc[r][NPAIR - 2]) : "l"(ap[r]), "l"(b1.x));
                    asm("fma.rn.f32x2 %0, %1, %2, %0;" : "+l"(acc[r][NPAIR - 1]) : "l"(ap[r]), "l"(b1.y));
                }
            }
        }
        __syncthreads();
    }

    // ---------------- epilogue ----------------
    if (epi == 4) {  // fused: mu | logvar -> outmlv, z -> zout (all fp32), TN==128
        const size_t n64 = (size_t)NN * 64;
#pragma unroll
        for (int r = 0; r < 8; r++) {
            int m = m0 + ty * 8 + r;
            if (m >= M) continue;
            float rs = g_dinv[m];
            float mu0, mu1, mu2, mu3, lv0, lv1, lv2, lv3;
            asm("mov.b64 {%0, %1}, %2;" : "=f"(mu0), "=f"(mu1) : "l"(acc[r][0]));
            asm("mov.b64 {%0, %1}, %2;" : "=f"(mu2), "=f"(mu3) : "l"(acc[r][1]));
            asm("mov.b64 {%0, %1}, %2;" : "=f"(lv0), "=f"(lv1) : "l"(acc[r][NPAIR - 2]));
            asm("mov.b64 {%0, %1}, %2;" : "=f"(lv2), "=f"(lv3) : "l"(acc[r][NPAIR - 1]));
            mu0 *= rs; mu1 *= rs; mu2 *= rs; mu3 *= rs;
            lv0 *= rs; lv1 *= rs; lv2 *= rs; lv3 *= rs;
            size_t base = (size_t)m * 64 + tx * 4;
            float4 ev = *reinterpret_cast<const float4*>(&eps[base]);
            float4 zv;
            zv.x = mu0 + ev.x * expf(0.5f * lv0);
            zv.y = mu1 + ev.y * expf(0.5f * lv1);
            zv.z = mu2 + ev.z * expf(0.5f * lv2);
            zv.w = mu3 + ev.w * expf(0.5f * lv3);
            *reinterpret_cast<float4*>(&outmlv[n64 + base])     = make_float4(mu0, mu1, mu2, mu3);
            *reinterpret_cast<float4*>(&outmlv[2 * n64 + base]) = make_float4(lv0, lv1, lv2, lv3);
            *reinterpret_cast<float4*>(&zout[base]) = zv;
        }
        return;
    }

    float4 bv0 = make_float4(0.f, 0.f, 0.f, 0.f), bv1 = bv0;
    if (epi == 1 || epi == 2) {
        bv0 = *reinterpret_cast<const float4*>(&bias[tx * 4]);
        if (TN == 128) bv1 = *reinterpret_cast<const float4*>(&bias[64 + tx * 4]);
    }
#pragma unroll
    for (int r = 0; r < 8; r++) {
        int m = m0 + ty * 8 + r;
        if (m >= M) continue;
        float rs = (epi == 3) ? g_dinv[m] : 1.0f;
        float f0, f1, f2, f3;
        asm("mov.b64 {%0, %1}, %2;" : "=f"(f0), "=f"(f1) : "l"(acc[r][0]));
        asm("mov.b64 {%0, %1}, %2;" : "=f"(f2), "=f"(f3) : "l"(acc[r][1]));
        float4 o;
        o.x = (f0 + bv0.x) * rs;
        o.y = (f1 + bv0.y) * rs;
        o.z = (f2 + bv0.z) * rs;
        o.w = (f3 + bv0.w) * rs;
        if (epi == 1) {
            o.x = fmaxf(o.x, 0.f); o.y = fmaxf(o.y, 0.f);
            o.z = fmaxf(o.z, 0.f); o.w = fmaxf(o.w, 0.f);
        }
        if (CH) *reinterpret_cast<uint2*>(&((__half*)Cp)[(size_t)m * TN + tx * 4]) = f4_to_h4(o);
        else    *reinterpret_cast<float4*>(&((float*)Cp)[(size_t)m * TN + tx * 4]) = o;
        if (TN == 128) {
            asm("mov.b64 {%0, %1}, %2;" : "=f"(f0), "=f"(f1) : "l"(acc[r][NPAIR - 2]));
            asm("mov.b64 {%0, %1}, %2;" : "=f"(f2), "=f"(f3) : "l"(acc[r][NPAIR - 1]));
            float4 p;
            p.x = (f0 + bv1.x) * rs;
            p.y = (f1 + bv1.y) * rs;
            p.z = (f2 + bv1.z) * rs;
            p.w = (f3 + bv1.w) * rs;
            if (epi == 1) {
                p.x = fmaxf(p.x, 0.f); p.y = fmaxf(p.y, 0.f);
                p.z = fmaxf(p.z, 0.f); p.w = fmaxf(p.w, 0.f);
            }
            if (CH) *reinterpret_cast<uint2*>(&((__half*)Cp)[(size_t)m * TN + 64 + tx * 4]) = f4_to_h4(p);
            else    *reinterpret_cast<float4*>(&((float*)Cp)[(size_t)m * TN + 64 + tx * 4]) = p;
        }
    }
}

// ---------------- launch ----------------
extern "C" void kernel_launch(void* const* d_in, const int* in_sizes, int n_in,
                              void* d_out, int out_size) {
    const float* x      = (const float*)d_in[0];
    const float* pseudo = (const float*)d_in[1];
    const float* w1     = (const float*)d_in[2];   // [3][64][128] == W1cat [192][128]
    const float* w2     = (const float*)d_in[3];   // [3][128][64] == W2cat [384][64]
    const float* mu_w   = (const float*)d_in[4];
    const float* lv_w   = (const float*)d_in[5];
    const float* d1_w   = (const float*)d_in[6];   // [64][128]
    const float* d1_b   = (const float*)d_in[7];
    const float* d2_w   = (const float*)d_in[8];   // [128][64]
    const float* d2_b   = (const float*)d_in[9];
    const float* eps    = (const float*)d_in[10];
    const void*  ei     = d_in[11];
    float*       out    = (float*)d_out;

    float *py, *ph1, *ph2, *pw3T;
    __half* px16;
    cudaGetSymbolAddress((void**)&py,   g_y);
    cudaGetSymbolAddress((void**)&ph1,  g_h1);
    cudaGetSymbolAddress((void**)&ph2,  g_h2);
    cudaGetSymbolAddress((void**)&pw3T, g_w3T);
    cudaGetSymbolAddress((void**)&px16, g_x16);

    const int GB = (NN + 127) / 128;

    // --- edge preprocessing + fp16 x copy ---
    k_prep<<<SCAN_B, 256>>>((const int*)ei, mu_w, lv_w);
    k_x16<<<(NN * 32 + 255) / 256, 256>>>(x);
    k_deg<<<(NE + 255) / 256, 256>>>(ei);
    k_scan1<<<SCAN_B, 256>>>();
    k_scan2<<<1, 512>>>();
    k_scan3<<<SCAN_B, 256>>>();
    k_place<<<(NE + 255) / 256, 256>>>(ei, pseudo);

    // --- layer 1: t1 = agg(x16) [fp32]; h1 = (t1 @ w1) * dinv -> fp16 ---
    k_agg64h<<<(NN * 16 + 255) / 256, 256>>>(px16, py);
    k_gemm2<128, false, true><<<GB, 256>>>(py, w1, nullptr, ph1, NN, 192, 3,
                                           nullptr, nullptr, nullptr);

    // --- layer 2: t2 = agg(h1) [fp16]; h2 = (t2 @ w2) * dinv -> fp16 ---
    k_agg128h<<<(NN * 32 + 255) / 256, 256>>>((const __half*)ph1, (__half*)py);
    k_gemm2<64, true, true><<<GB, 256>>>(py, w2, nullptr, ph2, NN, 384, 3,
                                         nullptr, nullptr, nullptr);

    // --- layer 3+4: t3 = agg(h2) [fp32]; mu/logvar -> out (fp32), z -> g_h1 (fp32) ---
    k_agg64h<<<(NN * 16 + 255) / 256, 256>>>((const __half*)ph2, py);
    k_gemm2<128, false, false><<<GB, 256>>>(py, pw3T, nullptr, nullptr, NN, 192, 4,
                                            eps, out, ph1);

    // --- decoder: hid = relu(z @ d1_w + b1) [fp32]; rec = hid @ d2_w + b2 ---
    k_gemm2<128, false, false><<<GB, 256>>>(ph1, d1_w, d1_b, py, NN, 64, 1,
                                            nullptr, nullptr, nullptr);
    k_gemm2<64, false, false><<<GB, 256>>>(py, d2_w, d2_b, out, NN, 128, 2,
                                           nullptr, nullptr, nullptr);
}